// round 2
// baseline (speedup 1.0000x reference)
#include <cuda_runtime.h>
#include <math.h>

// Problem constants
#define Bb   4
#define Tt   1024
#define Cc   1024
#define Hh   16
#define Dd   64
#define Ee   8
#define BOTd 64
#define Mrows 4096           // B*T
#define CH    4096           // 4*C

// ---------------- scratch (device globals; no allocation allowed) -----------
__device__ float g_h  [Mrows*Cc];
__device__ float g_q  [Mrows*Cc];
__device__ float g_k  [Mrows*Cc];
__device__ float g_v  [Mrows*Cc];
__device__ float g_y  [Mrows*Cc];
__device__ float g_x1 [Mrows*Cc];
__device__ float g_yad[Mrows*Cc];
__device__ float g_h2 [Mrows*Cc];
__device__ float g_mid[Mrows*CH];
__device__ int   g_gidx[Tt*2];
__device__ float g_gval[Tt*2];

// ---------------- LayerNorm: one block per row ------------------------------
__global__ __launch_bounds__(256)
void ln_k(const float* __restrict__ X, const float* __restrict__ G,
          const float* __restrict__ Bt, float* __restrict__ O)
{
    __shared__ float red[256];
    int row = blockIdx.x, tid = threadIdx.x;
    const float* xr = X + (size_t)row * Cc;
    float4 xv = *(const float4*)(xr + tid * 4);
    red[tid] = xv.x + xv.y + xv.z + xv.w;
    __syncthreads();
    #pragma unroll
    for (int st = 128; st > 0; st >>= 1) {
        if (tid < st) red[tid] += red[tid + st];
        __syncthreads();
    }
    float mu = red[0] * (1.f / 1024.f);
    __syncthreads();
    float d0 = xv.x - mu, d1 = xv.y - mu, d2 = xv.z - mu, d3 = xv.w - mu;
    red[tid] = d0*d0 + d1*d1 + d2*d2 + d3*d3;
    __syncthreads();
    #pragma unroll
    for (int st = 128; st > 0; st >>= 1) {
        if (tid < st) red[tid] += red[tid + st];
        __syncthreads();
    }
    float rs = rsqrtf(red[0] * (1.f / 1024.f) + 1e-5f);
    float4 gv = *(const float4*)(G  + tid * 4);
    float4 bv = *(const float4*)(Bt + tid * 4);
    float4 ov = make_float4(d0*rs*gv.x + bv.x, d1*rs*gv.y + bv.y,
                            d2*rs*gv.z + bv.z, d3*rs*gv.w + bv.w);
    *(float4*)(O + (size_t)row * Cc + tid * 4) = ov;
}

// ---------------- SGEMM 128x128x16, 256 threads, 8x8 microtile --------------
// EPI: 0 = +bias; 1 = +bias+R1; 2 = gelu(+bias); 3 = +bias+R1+R2
template<int EPI>
__global__ __launch_bounds__(256)
void gemm_k(const float* __restrict__ A, const float* __restrict__ W,
            const float* __restrict__ bias, const float* __restrict__ R1,
            const float* __restrict__ R2, float* __restrict__ O,
            int Md, int Nd, int Kd)
{
    __shared__ float As[16][128];
    __shared__ float Bs[16][128];
    int tid = threadIdx.x;
    int tx = tid & 15, ty = tid >> 4;
    int n0 = blockIdx.x * 128, m0 = blockIdx.y * 128;
    float acc[8][8];
    #pragma unroll
    for (int i = 0; i < 8; i++)
        #pragma unroll
        for (int j = 0; j < 8; j++) acc[i][j] = 0.f;

    for (int k0 = 0; k0 < Kd; k0 += 16) {
        #pragma unroll
        for (int l = 0; l < 2; l++) {
            int f = tid + l * 256;
            int am = f >> 2, ak = (f & 3) << 2;
            float4 av = *(const float4*)(A + (size_t)(m0 + am) * Kd + k0 + ak);
            As[ak+0][am] = av.x; As[ak+1][am] = av.y;
            As[ak+2][am] = av.z; As[ak+3][am] = av.w;
            int bk = f >> 5, bn = (f & 31) << 2;
            float4 wv = __ldg((const float4*)(W + (size_t)(k0 + bk) * Nd + n0 + bn));
            *(float4*)(&Bs[bk][bn]) = wv;
        }
        __syncthreads();
        #pragma unroll
        for (int kk = 0; kk < 16; kk++) {
            float a[8], b[8];
            *(float4*)(a)   = *(const float4*)(&As[kk][ty*8]);
            *(float4*)(a+4) = *(const float4*)(&As[kk][ty*8+4]);
            *(float4*)(b)   = *(const float4*)(&Bs[kk][tx*8]);
            *(float4*)(b+4) = *(const float4*)(&Bs[kk][tx*8+4]);
            #pragma unroll
            for (int i = 0; i < 8; i++)
                #pragma unroll
                for (int j = 0; j < 8; j++)
                    acc[i][j] += a[i] * b[j];
        }
        __syncthreads();
    }
    #pragma unroll
    for (int i = 0; i < 8; i++) {
        int m = m0 + ty * 8 + i;
        size_t base = (size_t)m * Nd + n0 + tx * 8;
        #pragma unroll
        for (int j = 0; j < 8; j++) {
            float v = acc[i][j] + bias[n0 + tx*8 + j];
            if (EPI == 1) v += R1[base + j];
            if (EPI == 2) v = 0.5f * v * (1.f + erff(v * 0.70710678118654752f));
            if (EPI == 3) v += R1[base + j] + R2[base + j];
            acc[i][j] = v;
        }
        *(float4*)(O + base)     = *(float4*)(&acc[i][0]);
        *(float4*)(O + base + 4) = *(float4*)(&acc[i][4]);
    }
}

// ---------------- Causal flash attention: 1 thread = 1 query row ------------
__global__ __launch_bounds__(128)
void attn_k(const float* __restrict__ Q, const float* __restrict__ K,
            const float* __restrict__ V, float* __restrict__ Y)
{
    __shared__ float Ks[64][64];
    __shared__ float Vs[64][64];
    int bh = blockIdx.y;
    int b = bh >> 4, h = bh & 15;
    int tid = threadIdx.x;
    int qt = blockIdx.x * 128 + tid;

    const float* qp = Q + ((size_t)(b * Tt + qt)) * Cc + h * Dd;
    float qr[64];
    #pragma unroll
    for (int d = 0; d < 64; d += 4) {
        float4 v4 = *(const float4*)(qp + d);
        qr[d]   = v4.x * 0.125f; qr[d+1] = v4.y * 0.125f;
        qr[d+2] = v4.z * 0.125f; qr[d+3] = v4.w * 0.125f;
    }
    float acc[64];
    #pragma unroll
    for (int d = 0; d < 64; d++) acc[d] = 0.f;
    float mval = -1e30f, lsum = 0.f;

    int smax = blockIdx.x * 128 + 127;
    for (int s0 = 0; s0 <= smax; s0 += 64) {
        #pragma unroll
        for (int l = 0; l < 8; l++) {
            int f = tid + l * 128;
            int r = f >> 4, c = (f & 15) << 2;
            size_t gof = ((size_t)(b * Tt + s0 + r)) * Cc + h * Dd + c;
            *(float4*)(&Ks[r][c]) = *(const float4*)(K + gof);
            *(float4*)(&Vs[r][c]) = *(const float4*)(V + gof);
        }
        __syncthreads();
        int send = qt - s0 + 1; if (send > 64) send = 64;
        for (int s = 0; s < send; s++) {
            float dot = 0.f;
            #pragma unroll
            for (int d = 0; d < 64; d++) dot += qr[d] * Ks[s][d];
            if (dot <= mval) {
                float p = __expf(dot - mval);
                lsum += p;
                #pragma unroll
                for (int d = 0; d < 64; d++) acc[d] += p * Vs[s][d];
            } else {
                float corr = __expf(mval - dot);
                mval = dot;
                lsum = lsum * corr + 1.f;
                #pragma unroll
                for (int d = 0; d < 64; d++) acc[d] = acc[d] * corr + Vs[s][d];
            }
        }
        __syncthreads();
    }
    float inv = 1.f / lsum;
    float* yp = Y + ((size_t)(b * Tt + qt)) * Cc + h * Dd;
    #pragma unroll
    for (int d = 0; d < 64; d += 4) {
        float4 o = make_float4(acc[d]*inv, acc[d+1]*inv, acc[d+2]*inv, acc[d+3]*inv);
        *(float4*)(yp + d) = o;
    }
}

// ---------------- Router + top-2 gating (batch 0 rows) ----------------------
__global__ __launch_bounds__(128)
void router_k(const float* __restrict__ X, const float* __restrict__ R,
              int* __restrict__ gidx, float* __restrict__ gval)
{
    __shared__ float red[128][8];
    int t = blockIdx.x, tid = threadIdx.x;
    const float* xr = X + (size_t)t * Cc;   // batch 0 == rows [0,T)
    float acc[8];
    #pragma unroll
    for (int e = 0; e < 8; e++) acc[e] = 0.f;
    for (int c = tid; c < Cc; c += 128) {
        float xv = xr[c];
        const float* rr = R + c * 8;
        #pragma unroll
        for (int e = 0; e < 8; e++) acc[e] += xv * rr[e];
    }
    #pragma unroll
    for (int e = 0; e < 8; e++) red[tid][e] = acc[e];
    __syncthreads();
    for (int st = 64; st > 0; st >>= 1) {
        if (tid < st)
            #pragma unroll
            for (int e = 0; e < 8; e++) red[tid][e] += red[tid + st][e];
        __syncthreads();
    }
    if (tid == 0) {
        float lg[8];
        #pragma unroll
        for (int e = 0; e < 8; e++) lg[e] = red[0][e];
        int i0 = 0;
        #pragma unroll
        for (int e = 1; e < 8; e++) if (lg[e] > lg[i0]) i0 = e;
        int i1 = (i0 == 0) ? 1 : 0;
        #pragma unroll
        for (int e = 0; e < 8; e++) if (e != i0 && lg[e] > lg[i1]) i1 = e;
        float b2  = expf(lg[i1] - lg[i0]);
        float inv = 1.f / (1.f + b2);
        gidx[2*t] = i0; gidx[2*t+1] = i1;
        gval[2*t] = inv; gval[2*t+1] = b2 * inv;
    }
}

// ---------------- Sparse top-2 adapter: one block per (b,t) row -------------
__global__ __launch_bounds__(256)
void adapter_k(const float* __restrict__ X, const float* __restrict__ AD_W,
               const float* __restrict__ AD_B, const float* __restrict__ AU_W,
               const float* __restrict__ AU_B, const int* __restrict__ gidx,
               const float* __restrict__ gval, float* __restrict__ YAD)
{
    __shared__ float xs[Cc];
    __shared__ float part[4][BOTd];
    __shared__ float down[BOTd];
    int row = blockIdx.x;
    int t   = row & (Tt - 1);
    int tid = threadIdx.x;
    for (int c = tid; c < Cc; c += 256) xs[c] = X[(size_t)row * Cc + c];
    __syncthreads();

    float outv[4] = {0.f, 0.f, 0.f, 0.f};
    for (int kk = 0; kk < 2; kk++) {
        int e = gidx[2*t + kk];
        float gate = gval[2*t + kk] * 0.1f;
        int j = tid & 63, grp = tid >> 6;
        const float* w = AD_W + (size_t)e * Cc * BOTd;
        float p = 0.f;
        for (int c = grp; c < Cc; c += 4) p += xs[c] * __ldg(w + c * BOTd + j);
        part[grp][j] = p;
        __syncthreads();
        if (tid < 64) {
            float d = part[0][tid] + part[1][tid] + part[2][tid] + part[3][tid]
                    + AD_B[e * BOTd + tid];
            down[tid] = fmaxf(d, 0.f);
        }
        __syncthreads();
        const float* wu = AU_W + (size_t)e * BOTd * Cc;
        #pragma unroll
        for (int i = 0; i < 4; i++) {
            int c = tid + i * 256;
            float v = AU_B[e * Cc + c];
            #pragma unroll 8
            for (int jj = 0; jj < 64; jj++) v += down[jj] * __ldg(wu + jj * Cc + c);
            outv[i] += gate * v;
        }
        __syncthreads();
    }
    #pragma unroll
    for (int i = 0; i < 4; i++)
        YAD[(size_t)row * Cc + tid + i * 256] = outv[i];
}

// ---------------- launch ----------------------------------------------------
extern "C" void kernel_launch(void* const* d_in, const int* in_sizes, int n_in,
                              void* d_out, int out_size)
{
    const float* x      = (const float*)d_in[0];
    const float* Wq     = (const float*)d_in[1];
    const float* bq     = (const float*)d_in[2];
    const float* Wk     = (const float*)d_in[3];
    const float* bk     = (const float*)d_in[4];
    const float* Wv     = (const float*)d_in[5];
    const float* bv     = (const float*)d_in[6];
    const float* Wo     = (const float*)d_in[7];
    const float* bo     = (const float*)d_in[8];
    const float* ln1_g  = (const float*)d_in[9];
    const float* ln1_b  = (const float*)d_in[10];
    const float* ln2_g  = (const float*)d_in[11];
    const float* ln2_b  = (const float*)d_in[12];
    const float* mlp_w1 = (const float*)d_in[13];
    const float* mlp_b1 = (const float*)d_in[14];
    const float* mlp_w2 = (const float*)d_in[15];
    const float* mlp_b2 = (const float*)d_in[16];
    const float* router = (const float*)d_in[17];
    const float* ad_w   = (const float*)d_in[18];
    const float* ad_b   = (const float*)d_in[19];
    const float* au_w   = (const float*)d_in[20];
    const float* au_b   = (const float*)d_in[21];

    float *h, *q, *k, *v, *y, *x1, *yad, *h2, *mid, *gval;
    int *gidx;
    cudaGetSymbolAddress((void**)&h,   g_h);
    cudaGetSymbolAddress((void**)&q,   g_q);
    cudaGetSymbolAddress((void**)&k,   g_k);
    cudaGetSymbolAddress((void**)&v,   g_v);
    cudaGetSymbolAddress((void**)&y,   g_y);
    cudaGetSymbolAddress((void**)&x1,  g_x1);
    cudaGetSymbolAddress((void**)&yad, g_yad);
    cudaGetSymbolAddress((void**)&h2,  g_h2);
    cudaGetSymbolAddress((void**)&mid, g_mid);
    cudaGetSymbolAddress((void**)&gidx, g_gidx);
    cudaGetSymbolAddress((void**)&gval, g_gval);

    float* out = (float*)d_out;
    dim3 gemmB(256);
    dim3 gProj(Cc / 128, Mrows / 128);   // (8, 32)
    dim3 gMlp1(CH / 128, Mrows / 128);   // (32, 32)

    // h = LN1(x)
    ln_k<<<Mrows, 256>>>(x, ln1_g, ln1_b, h);
    // q,k,v projections
    gemm_k<0><<<gProj, gemmB>>>(h, Wq, bq, nullptr, nullptr, q, Mrows, Cc, Cc);
    gemm_k<0><<<gProj, gemmB>>>(h, Wk, bk, nullptr, nullptr, k, Mrows, Cc, Cc);
    gemm_k<0><<<gProj, gemmB>>>(h, Wv, bv, nullptr, nullptr, v, Mrows, Cc, Cc);
    // causal attention
    attn_k<<<dim3(Tt / 128, Bb * Hh), 128>>>(q, k, v, y);
    // x1 = x + y @ Wo + bo
    gemm_k<1><<<gProj, gemmB>>>(y, Wo, bo, x, nullptr, x1, Mrows, Cc, Cc);
    // router gates (batch 0)
    router_k<<<Tt, 128>>>(x1, router, gidx, gval);
    // sparse top-2 adapter
    adapter_k<<<Mrows, 256>>>(x1, ad_w, ad_b, au_w, au_b, gidx, gval, yad);
    // h2 = LN2(x1)
    ln_k<<<Mrows, 256>>>(x1, ln2_g, ln2_b, h2);
    // mid = gelu(h2 @ w1 + b1)
    gemm_k<2><<<gMlp1, gemmB>>>(h2, mlp_w1, mlp_b1, nullptr, nullptr, mid, Mrows, CH, Cc);
    // out = x1 + (mid @ w2 + b2) + yad
    gemm_k<3><<<gProj, gemmB>>>(mid, mlp_w2, mlp_b2, x1, yad, out, Mrows, Cc, CH);
}

// round 6
// speedup vs baseline: 1.9644x; 1.9644x over previous
#include <cuda_runtime.h>
#include <math.h>
#include <stdint.h>

// Problem constants
#define Bb   4
#define Tt   1024
#define Cc   1024
#define Hh   16
#define Dd   64
#define Ee   8
#define BOTd 64
#define Mrows 4096           // B*T
#define CH    4096           // 4*C

// ---------------- scratch (device globals; no allocation allowed) -----------
__device__ float g_h  [Mrows*Cc];
__device__ float g_q  [Mrows*Cc];
__device__ float g_k  [Mrows*Cc];
__device__ float g_v  [Mrows*Cc];
__device__ float g_y  [Mrows*Cc];
__device__ float g_x1 [Mrows*Cc];
__device__ float g_yad[Mrows*Cc];
__device__ float g_h2 [Mrows*Cc];
__device__ float g_mid[Mrows*CH];
__device__ int   g_gidx[Tt*2];
__device__ float g_gval[Tt*2];
// transposed weights (K-major B operands: Wt[N][K])
__device__ float g_wqt[Cc*Cc];
__device__ float g_wkt[Cc*Cc];
__device__ float g_wvt[Cc*Cc];
__device__ float g_wot[Cc*Cc];
__device__ float g_w1t[Cc*CH];
__device__ float g_w2t[CH*Cc];

// cvt.rna.tf32.f32 needs a .b32 destination register
__device__ __forceinline__ uint32_t tf32r(float x) {
    uint32_t r; asm("cvt.rna.tf32.f32 %0, %1;" : "=r"(r) : "f"(x)); return r;
}

// ---------------- TF32 mma.sync GEMM: 128x128 tile, K-chunk 32 ---------------
// 8 warps in 4(m) x 2(n); warp tile 32x64 = 2x8 m16n8k8 tiles.
// EPI: 0 = +bias; 1 = +bias+R1; 2 = gelu(+bias); 3 = +bias+R1+R2
#define SMS 36   // smem row stride (32-bit words): conflict-free fragment loads

template<int EPI>
__global__ __launch_bounds__(256)
void mma_gemm(const float* __restrict__ A, const float* __restrict__ Wt,
              const float* __restrict__ bias, const float* __restrict__ R1,
              const float* __restrict__ R2, float* __restrict__ O,
              int Md, int Nd, int Kd)
{
    __shared__ uint32_t As[128 * SMS];
    __shared__ uint32_t Bs[128 * SMS];
    int tid = threadIdx.x, wid = tid >> 5, lid = tid & 31;
    int wm = wid & 3, wn = wid >> 2;
    int g = lid >> 2, t = lid & 3;
    int n0 = blockIdx.x * 128, m0 = blockIdx.y * 128;

    float d[2][8][4];
    #pragma unroll
    for (int mt = 0; mt < 2; mt++)
        #pragma unroll
        for (int nt = 0; nt < 8; nt++)
            #pragma unroll
            for (int r = 0; r < 4; r++) d[mt][nt][r] = 0.f;

    int ldrow = tid >> 3;              // tid/8 = 0..31; 4 strided row groups
    int ldcq  = (tid & 7) << 2;        // col 0..28 step 4

    const int NC = Kd >> 5;
    float4 av[4], bv[4];

    // prologue: load + store chunk 0
    #pragma unroll
    for (int l = 0; l < 4; l++) {
        int row = ldrow + l * 32;
        av[l] = *(const float4*)(A  + (size_t)(m0 + row) * Kd + ldcq);
        bv[l] = *(const float4*)(Wt + (size_t)(n0 + row) * Kd + ldcq);
    }
    #pragma unroll
    for (int l = 0; l < 4; l++) {
        int row = ldrow + l * 32;
        uint32_t* ap = &As[row * SMS + ldcq];
        ap[0] = tf32r(av[l].x); ap[1] = tf32r(av[l].y);
        ap[2] = tf32r(av[l].z); ap[3] = tf32r(av[l].w);
        uint32_t* bp = &Bs[row * SMS + ldcq];
        bp[0] = tf32r(bv[l].x); bp[1] = tf32r(bv[l].y);
        bp[2] = tf32r(bv[l].z); bp[3] = tf32r(bv[l].w);
    }
    __syncthreads();

    for (int i = 0; i < NC; i++) {
        // prefetch next chunk into registers (overlaps with mma below)
        if (i + 1 < NC) {
            int k0 = (i + 1) << 5;
            #pragma unroll
            for (int l = 0; l < 4; l++) {
                int row = ldrow + l * 32;
                av[l] = *(const float4*)(A  + (size_t)(m0 + row) * Kd + k0 + ldcq);
                bv[l] = *(const float4*)(Wt + (size_t)(n0 + row) * Kd + k0 + ldcq);
            }
        }
        // compute 4 k8 steps on current smem
        #pragma unroll
        for (int kk = 0; kk < 4; kk++) {
            int kb = kk * 8;
            uint32_t a[2][4];
            #pragma unroll
            for (int mt = 0; mt < 2; mt++) {
                int r = wm * 32 + mt * 16 + g;
                a[mt][0] = As[r * SMS + kb + t];
                a[mt][1] = As[(r + 8) * SMS + kb + t];
                a[mt][2] = As[r * SMS + kb + t + 4];
                a[mt][3] = As[(r + 8) * SMS + kb + t + 4];
            }
            #pragma unroll
            for (int nt = 0; nt < 8; nt++) {
                int n = wn * 64 + nt * 8 + g;
                uint32_t b0 = Bs[n * SMS + kb + t];
                uint32_t b1 = Bs[n * SMS + kb + t + 4];
                #pragma unroll
                for (int mt = 0; mt < 2; mt++) {
                    asm volatile(
                        "mma.sync.aligned.m16n8k8.row.col.f32.tf32.tf32.f32 "
                        "{%0,%1,%2,%3}, {%4,%5,%6,%7}, {%8,%9}, {%0,%1,%2,%3};"
                        : "+f"(d[mt][nt][0]), "+f"(d[mt][nt][1]),
                          "+f"(d[mt][nt][2]), "+f"(d[mt][nt][3])
                        : "r"(a[mt][0]), "r"(a[mt][1]), "r"(a[mt][2]), "r"(a[mt][3]),
                          "r"(b0), "r"(b1));
                }
            }
        }
        if (i + 1 < NC) {
            __syncthreads();
            #pragma unroll
            for (int l = 0; l < 4; l++) {
                int row = ldrow + l * 32;
                uint32_t* ap = &As[row * SMS + ldcq];
                ap[0] = tf32r(av[l].x); ap[1] = tf32r(av[l].y);
                ap[2] = tf32r(av[l].z); ap[3] = tf32r(av[l].w);
                uint32_t* bp = &Bs[row * SMS + ldcq];
                bp[0] = tf32r(bv[l].x); bp[1] = tf32r(bv[l].y);
                bp[2] = tf32r(bv[l].z); bp[3] = tf32r(bv[l].w);
            }
            __syncthreads();
        }
    }

    // ---- epilogue ----
    #pragma unroll
    for (int mt = 0; mt < 2; mt++) {
        int r0 = m0 + wm * 32 + mt * 16 + g;
        #pragma unroll
        for (int nt = 0; nt < 8; nt++) {
            int c = n0 + wn * 64 + nt * 8 + 2 * t;
            float bx = bias[c], by = bias[c + 1];
            #pragma unroll
            for (int hrow = 0; hrow < 2; hrow++) {
                int r = r0 + hrow * 8;
                size_t base = (size_t)r * Nd + c;
                float vx = d[mt][nt][hrow * 2]     + bx;
                float vy = d[mt][nt][hrow * 2 + 1] + by;
                if (EPI == 1) {
                    float2 r1 = *(const float2*)(R1 + base);
                    vx += r1.x; vy += r1.y;
                }
                if (EPI == 2) {
                    vx = 0.5f * vx * (1.f + erff(vx * 0.70710678118654752f));
                    vy = 0.5f * vy * (1.f + erff(vy * 0.70710678118654752f));
                }
                if (EPI == 3) {
                    float2 r1 = *(const float2*)(R1 + base);
                    float2 r2 = *(const float2*)(R2 + base);
                    vx += r1.x + r2.x; vy += r1.y + r2.y;
                }
                float2 o = make_float2(vx, vy);
                *(float2*)(O + base) = o;
            }
        }
    }
}

// ---------------- weight transpose: in[K][N] -> out[N][K] --------------------
__global__ __launch_bounds__(256)
void transpose_k(const float* __restrict__ in, float* __restrict__ out,
                 int K, int N)
{
    __shared__ float t[32][33];
    int kb = blockIdx.y * 32, nb = blockIdx.x * 32;
    int x = threadIdx.x, y = threadIdx.y;   // 32 x 8
    #pragma unroll
    for (int dy = 0; dy < 32; dy += 8)
        t[y + dy][x] = in[(size_t)(kb + y + dy) * N + nb + x];
    __syncthreads();
    #pragma unroll
    for (int dy = 0; dy < 32; dy += 8)
        out[(size_t)(nb + y + dy) * K + kb + x] = t[x][y + dy];
}

// ---------------- LayerNorm: one block per row ------------------------------
__global__ __launch_bounds__(256)
void ln_k(const float* __restrict__ X, const float* __restrict__ G,
          const float* __restrict__ Bt, float* __restrict__ O)
{
    __shared__ float red[256];
    int row = blockIdx.x, tid = threadIdx.x;
    const float* xr = X + (size_t)row * Cc;
    float4 xv = *(const float4*)(xr + tid * 4);
    red[tid] = xv.x + xv.y + xv.z + xv.w;
    __syncthreads();
    #pragma unroll
    for (int st = 128; st > 0; st >>= 1) {
        if (tid < st) red[tid] += red[tid + st];
        __syncthreads();
    }
    float mu = red[0] * (1.f / 1024.f);
    __syncthreads();
    float d0 = xv.x - mu, d1 = xv.y - mu, d2 = xv.z - mu, d3 = xv.w - mu;
    red[tid] = d0*d0 + d1*d1 + d2*d2 + d3*d3;
    __syncthreads();
    #pragma unroll
    for (int st = 128; st > 0; st >>= 1) {
        if (tid < st) red[tid] += red[tid + st];
        __syncthreads();
    }
    float rs = rsqrtf(red[0] * (1.f / 1024.f) + 1e-5f);
    float4 gv = *(const float4*)(G  + tid * 4);
    float4 bv = *(const float4*)(Bt + tid * 4);
    float4 ov = make_float4(d0*rs*gv.x + bv.x, d1*rs*gv.y + bv.y,
                            d2*rs*gv.z + bv.z, d3*rs*gv.w + bv.w);
    *(float4*)(O + (size_t)row * Cc + tid * 4) = ov;
}

// ---------------- Causal flash attention: 1 thread = 1 query row ------------
__global__ __launch_bounds__(128)
void attn_k(const float* __restrict__ Q, const float* __restrict__ K,
            const float* __restrict__ V, float* __restrict__ Y)
{
    __shared__ float Ks[64][64];
    __shared__ float Vs[64][64];
    int bh = blockIdx.y;
    int b = bh >> 4, h = bh & 15;
    int tid = threadIdx.x;
    int qt = blockIdx.x * 128 + tid;

    const float* qp = Q + ((size_t)(b * Tt + qt)) * Cc + h * Dd;
    float qr[64];
    #pragma unroll
    for (int d = 0; d < 64; d += 4) {
        float4 v4 = *(const float4*)(qp + d);
        qr[d]   = v4.x * 0.125f; qr[d+1] = v4.y * 0.125f;
        qr[d+2] = v4.z * 0.125f; qr[d+3] = v4.w * 0.125f;
    }
    float acc[64];
    #pragma unroll
    for (int d = 0; d < 64; d++) acc[d] = 0.f;
    float mval = -1e30f, lsum = 0.f;

    int smax = blockIdx.x * 128 + 127;
    for (int s0 = 0; s0 <= smax; s0 += 64) {
        #pragma unroll
        for (int l = 0; l < 8; l++) {
            int f = tid + l * 128;
            int r = f >> 4, c = (f & 15) << 2;
            size_t gof = ((size_t)(b * Tt + s0 + r)) * Cc + h * Dd + c;
            *(float4*)(&Ks[r][c]) = *(const float4*)(K + gof);
            *(float4*)(&Vs[r][c]) = *(const float4*)(V + gof);
        }
        __syncthreads();
        int send = qt - s0 + 1; if (send > 64) send = 64;
        for (int s = 0; s < send; s++) {
            float dot = 0.f;
            #pragma unroll
            for (int d = 0; d < 64; d++) dot += qr[d] * Ks[s][d];
            if (dot <= mval) {
                float p = __expf(dot - mval);
                lsum += p;
                #pragma unroll
                for (int d = 0; d < 64; d++) acc[d] += p * Vs[s][d];
            } else {
                float corr = __expf(mval - dot);
                mval = dot;
                lsum = lsum * corr + 1.f;
                #pragma unroll
                for (int d = 0; d < 64; d++) acc[d] = acc[d] * corr + Vs[s][d];
            }
        }
        __syncthreads();
    }
    float inv = 1.f / lsum;
    float* yp = Y + ((size_t)(b * Tt + qt)) * Cc + h * Dd;
    #pragma unroll
    for (int d = 0; d < 64; d += 4) {
        float4 o = make_float4(acc[d]*inv, acc[d+1]*inv, acc[d+2]*inv, acc[d+3]*inv);
        *(float4*)(yp + d) = o;
    }
}

// ---------------- Router + top-2 gating (batch 0 rows) ----------------------
__global__ __launch_bounds__(128)
void router_k(const float* __restrict__ X, const float* __restrict__ R,
              int* __restrict__ gidx, float* __restrict__ gval)
{
    __shared__ float red[128][8];
    int t = blockIdx.x, tid = threadIdx.x;
    const float* xr = X + (size_t)t * Cc;   // batch 0 == rows [0,T)
    float acc[8];
    #pragma unroll
    for (int e = 0; e < 8; e++) acc[e] = 0.f;
    for (int c = tid; c < Cc; c += 128) {
        float xv = xr[c];
        const float* rr = R + c * 8;
        #pragma unroll
        for (int e = 0; e < 8; e++) acc[e] += xv * rr[e];
    }
    #pragma unroll
    for (int e = 0; e < 8; e++) red[tid][e] = acc[e];
    __syncthreads();
    for (int st = 64; st > 0; st >>= 1) {
        if (tid < st)
            #pragma unroll
            for (int e = 0; e < 8; e++) red[tid][e] += red[tid + st][e];
        __syncthreads();
    }
    if (tid == 0) {
        float lg[8];
        #pragma unroll
        for (int e = 0; e < 8; e++) lg[e] = red[0][e];
        int i0 = 0;
        #pragma unroll
        for (int e = 1; e < 8; e++) if (lg[e] > lg[i0]) i0 = e;
        int i1 = (i0 == 0) ? 1 : 0;
        #pragma unroll
        for (int e = 0; e < 8; e++) if (e != i0 && lg[e] > lg[i1]) i1 = e;
        float b2  = expf(lg[i1] - lg[i0]);
        float inv = 1.f / (1.f + b2);
        gidx[2*t] = i0; gidx[2*t+1] = i1;
        gval[2*t] = inv; gval[2*t+1] = b2 * inv;
    }
}

// ---------------- Sparse top-2 adapter: one block per (b,t) row -------------
__global__ __launch_bounds__(256)
void adapter_k(const float* __restrict__ X, const float* __restrict__ AD_W,
               const float* __restrict__ AD_B, const float* __restrict__ AU_W,
               const float* __restrict__ AU_B, const int* __restrict__ gidx,
               const float* __restrict__ gval, float* __restrict__ YAD)
{
    __shared__ float xs[Cc];
    __shared__ float part[4][BOTd];
    __shared__ float down[BOTd];
    int row = blockIdx.x;
    int t   = row & (Tt - 1);
    int tid = threadIdx.x;
    for (int c = tid; c < Cc; c += 256) xs[c] = X[(size_t)row * Cc + c];
    __syncthreads();

    float outv[4] = {0.f, 0.f, 0.f, 0.f};
    for (int kk = 0; kk < 2; kk++) {
        int e = gidx[2*t + kk];
        float gate = gval[2*t + kk] * 0.1f;
        int j = tid & 63, grp = tid >> 6;
        const float* w = AD_W + (size_t)e * Cc * BOTd;
        float p = 0.f;
        for (int c = grp; c < Cc; c += 4) p += xs[c] * __ldg(w + c * BOTd + j);
        part[grp][j] = p;
        __syncthreads();
        if (tid < 64) {
            float d = part[0][tid] + part[1][tid] + part[2][tid] + part[3][tid]
                    + AD_B[e * BOTd + tid];
            down[tid] = fmaxf(d, 0.f);
        }
        __syncthreads();
        const float* wu = AU_W + (size_t)e * BOTd * Cc;
        #pragma unroll
        for (int i = 0; i < 4; i++) {
            int c = tid + i * 256;
            float v = AU_B[e * Cc + c];
            #pragma unroll 8
            for (int jj = 0; jj < 64; jj++) v += down[jj] * __ldg(wu + jj * Cc + c);
            outv[i] += gate * v;
        }
        __syncthreads();
    }
    #pragma unroll
    for (int i = 0; i < 4; i++)
        YAD[(size_t)row * Cc + tid + i * 256] = outv[i];
}

// ---------------- launch ----------------------------------------------------
extern "C" void kernel_launch(void* const* d_in, const int* in_sizes, int n_in,
                              void* d_out, int out_size)
{
    const float* x      = (const float*)d_in[0];
    const float* Wq     = (const float*)d_in[1];
    const float* bq     = (const float*)d_in[2];
    const float* Wk     = (const float*)d_in[3];
    const float* bk     = (const float*)d_in[4];
    const float* Wv     = (const float*)d_in[5];
    const float* bv     = (const float*)d_in[6];
    const float* Wo     = (const float*)d_in[7];
    const float* bo     = (const float*)d_in[8];
    const float* ln1_g  = (const float*)d_in[9];
    const float* ln1_b  = (const float*)d_in[10];
    const float* ln2_g  = (const float*)d_in[11];
    const float* ln2_b  = (const float*)d_in[12];
    const float* mlp_w1 = (const float*)d_in[13];
    const float* mlp_b1 = (const float*)d_in[14];
    const float* mlp_w2 = (const float*)d_in[15];
    const float* mlp_b2 = (const float*)d_in[16];
    const float* router = (const float*)d_in[17];
    const float* ad_w   = (const float*)d_in[18];
    const float* ad_b   = (const float*)d_in[19];
    const float* au_w   = (const float*)d_in[20];
    const float* au_b   = (const float*)d_in[21];

    float *h, *q, *k, *v, *y, *x1, *yad, *h2, *mid, *gval;
    float *wqt, *wkt, *wvt, *wot, *w1t, *w2t;
    int *gidx;
    cudaGetSymbolAddress((void**)&h,   g_h);
    cudaGetSymbolAddress((void**)&q,   g_q);
    cudaGetSymbolAddress((void**)&k,   g_k);
    cudaGetSymbolAddress((void**)&v,   g_v);
    cudaGetSymbolAddress((void**)&y,   g_y);
    cudaGetSymbolAddress((void**)&x1,  g_x1);
    cudaGetSymbolAddress((void**)&yad, g_yad);
    cudaGetSymbolAddress((void**)&h2,  g_h2);
    cudaGetSymbolAddress((void**)&mid, g_mid);
    cudaGetSymbolAddress((void**)&gidx, g_gidx);
    cudaGetSymbolAddress((void**)&gval, g_gval);
    cudaGetSymbolAddress((void**)&wqt, g_wqt);
    cudaGetSymbolAddress((void**)&wkt, g_wkt);
    cudaGetSymbolAddress((void**)&wvt, g_wvt);
    cudaGetSymbolAddress((void**)&wot, g_wot);
    cudaGetSymbolAddress((void**)&w1t, g_w1t);
    cudaGetSymbolAddress((void**)&w2t, g_w2t);

    float* out = (float*)d_out;
    dim3 tb(32, 8);
    // weight transposes: in[K][N] -> out[N][K]
    transpose_k<<<dim3(Cc/32, Cc/32), tb>>>(Wq, wqt, Cc, Cc);
    transpose_k<<<dim3(Cc/32, Cc/32), tb>>>(Wk, wkt, Cc, Cc);
    transpose_k<<<dim3(Cc/32, Cc/32), tb>>>(Wv, wvt, Cc, Cc);
    transpose_k<<<dim3(Cc/32, Cc/32), tb>>>(Wo, wot, Cc, Cc);
    transpose_k<<<dim3(CH/32, Cc/32), tb>>>(mlp_w1, w1t, Cc, CH);
    transpose_k<<<dim3(Cc/32, CH/32), tb>>>(mlp_w2, w2t, CH, Cc);

    dim3 gProj(Cc / 128, Mrows / 128);   // (8, 32)
    dim3 gMlp1(CH / 128, Mrows / 128);   // (32, 32)

    // h = LN1(x)
    ln_k<<<Mrows, 256>>>(x, ln1_g, ln1_b, h);
    // q,k,v projections (tf32 mma.sync)
    mma_gemm<0><<<gProj, 256>>>(h, wqt, bq, nullptr, nullptr, q, Mrows, Cc, Cc);
    mma_gemm<0><<<gProj, 256>>>(h, wkt, bk, nullptr, nullptr, k, Mrows, Cc, Cc);
    mma_gemm<0><<<gProj, 256>>>(h, wvt, bv, nullptr, nullptr, v, Mrows, Cc, Cc);
    // causal attention
    attn_k<<<dim3(Tt / 128, Bb * Hh), 128>>>(q, k, v, y);
    // x1 = x + y @ Wo + bo
    mma_gemm<1><<<gProj, 256>>>(y, wot, bo, x, nullptr, x1, Mrows, Cc, Cc);
    // router gates (batch 0)
    router_k<<<Tt, 128>>>(x1, router, gidx, gval);
    // sparse top-2 adapter
    adapter_k<<<Mrows, 256>>>(x1, ad_w, ad_b, au_w, au_b, gidx, gval, yad);
    // h2 = LN2(x1)
    ln_k<<<Mrows, 256>>>(x1, ln2_g, ln2_b, h2);
    // mid = gelu(h2 @ w1 + b1)
    mma_gemm<2><<<gMlp1, 256>>>(h2, w1t, mlp_b1, nullptr, nullptr, mid, Mrows, CH, Cc);
    // out = x1 + (mid @ w2 + b2) + yad
    mma_gemm<3><<<gProj, 256>>>(mid, w2t, mlp_b2, x1, yad, out, Mrows, Cc, CH);
}